// round 13
// baseline (speedup 1.0000x reference)
#include <cuda_runtime.h>
#include <math_constants.h>

// ---------------------------------------------------------------------------
// EwaldReciprocal: B=2, N=4096, NK=4096 — 3 launches.
//   sf:     2 k/thread, unconditional partials (MUFU floor, ~19.8us) [R10].
//   reduce: partials + expfac -> amplitude-phase: A*cos(th - phi)     [R10].
//   recip:  4 atoms/thread, grid 888 = 6/SM single wave, 1 MUFU/theta,
//           0.5 LDS/theta; fused finalize + state reset.
// ---------------------------------------------------------------------------

#define NCH    74                  // sf z-chunks (R10)
#define RNCH   111                 // recip z-chunks: 4*2*111 = 888 = 6/SM wave
#define MAXK   4096
#define MAXBN  32768

__device__ float2 g_Spart[NCH * 2 * MAXK];     // [z][b][k]
__device__ float4 g_t1[2 * MAXK];              // (kc.x, kc.y, kc.z, -phi) [b][k]
__device__ float  g_amp[2 * MAXK];             // A [b][k]
__device__ float  g_recip[MAXBN];              // zero at entry; re-zeroed at end
__device__ int    g_cnt_rc[64];

// ---------------- kernel 1: structure factor partials (R10 exact) -----------
#define SF_BLK 256
__global__ void __launch_bounds__(SF_BLK, 8)
sf_kernel(const float* __restrict__ coords,
          const float* __restrict__ q,
          const float* __restrict__ kvec,
          const float* __restrict__ cell_inv,
          int N, int NK, int nchunk) {
    __shared__ float4 sh[SF_BLK];
    int b  = blockIdx.y;
    int z  = blockIdx.z;
    int kA = blockIdx.x * (SF_BLK * 2) + threadIdx.x;
    int kB = kA + SF_BLK;
    int n0 = z * nchunk;
    int n1 = min(n0 + nchunk, N);

    const float twopi = 6.283185307179586f;
    float ci[9];
    #pragma unroll
    for (int i = 0; i < 9; i++) ci[i] = __ldg(&cell_inv[i]);

    float4 kcA = make_float4(0.f, 0.f, 0.f, 0.f);
    float4 kcB = make_float4(0.f, 0.f, 0.f, 0.f);
    if (kA < NK) {
        float kx = kvec[kA * 3 + 0], ky = kvec[kA * 3 + 1], kz = kvec[kA * 3 + 2];
        kcA.x = twopi * (kx * ci[0] + ky * ci[3] + kz * ci[6]);
        kcA.y = twopi * (kx * ci[1] + ky * ci[4] + kz * ci[7]);
        kcA.z = twopi * (kx * ci[2] + ky * ci[5] + kz * ci[8]);
    }
    if (kB < NK) {
        float kx = kvec[kB * 3 + 0], ky = kvec[kB * 3 + 1], kz = kvec[kB * 3 + 2];
        kcB.x = twopi * (kx * ci[0] + ky * ci[3] + kz * ci[6]);
        kcB.y = twopi * (kx * ci[1] + ky * ci[4] + kz * ci[7]);
        kcB.z = twopi * (kx * ci[2] + ky * ci[5] + kz * ci[8]);
    }

    float sreA = 0.f, simA = 0.f, sreB = 0.f, simB = 0.f;

    for (int t = n0; t < n1; t += SF_BLK) {
        int nt = min(SF_BLK, n1 - t);
        if ((int)threadIdx.x < nt) {
            int n = t + threadIdx.x;
            const float* cp = coords + ((size_t)b * N + n) * 3;
            sh[threadIdx.x] = make_float4(cp[0], cp[1], cp[2], q[(size_t)b * N + n]);
        }
        __syncthreads();
        #pragma unroll 4
        for (int j = 0; j < nt; j++) {
            float4 a = sh[j];
            float thA = fmaf(kcA.x, a.x, fmaf(kcA.y, a.y, kcA.z * a.z));
            float thB = fmaf(kcB.x, a.x, fmaf(kcB.y, a.y, kcB.z * a.z));
            float sA, cA, sB, cB;
            __sincosf(thA, &sA, &cA);
            __sincosf(thB, &sB, &cB);
            sreA = fmaf(a.w, cA, sreA);
            simA = fmaf(a.w, sA, simA);
            sreB = fmaf(a.w, cB, sreB);
            simB = fmaf(a.w, sB, simB);
        }
        __syncthreads();
    }
    if (kA < NK) g_Spart[(z * 2 + b) * NK + kA] = make_float2(sreA, simA);
    if (kB < NK) g_Spart[(z * 2 + b) * NK + kB] = make_float2(sreB, simB);
}

// ---------------- kernel 2: reduce partials -> amplitude-phase (R10 exact) ---
__global__ void reduce_kernel(const float* __restrict__ kvec,
                              const float* __restrict__ cell_inv,
                              const float* __restrict__ expfac,
                              int NK, int BK) {
    int i = blockIdx.x * blockDim.x + threadIdx.x;
    if (i >= BK) return;
    int b = i / NK;
    int k = i - b * NK;

    float sre = 0.f, sim = 0.f;
    #pragma unroll 8
    for (int zz = 0; zz < NCH; zz++) {
        float2 p = g_Spart[(zz * 2 + b) * NK + k];
        sre += p.x; sim += p.y;
    }
    const float twopi = 6.283185307179586f;
    float ci[9];
    #pragma unroll
    for (int j = 0; j < 9; j++) ci[j] = __ldg(&cell_inv[j]);
    float kx = kvec[k * 3 + 0], ky = kvec[k * 3 + 1], kz = kvec[k * 3 + 2];
    float kcx = twopi * (kx * ci[0] + ky * ci[3] + kz * ci[6]);
    float kcy = twopi * (kx * ci[1] + ky * ci[4] + kz * ci[7]);
    float kcz = twopi * (kx * ci[2] + ky * ci[5] + kz * ci[8]);
    float e = expfac[k];
    float er = e * sre;
    float ei = e * sim;
    // er*cos(th) + ei*sin(th) = A*cos(th - phi)
    float A   = sqrtf(er * er + ei * ei);
    float phi = atan2f(ei, er);
    g_t1[i]  = make_float4(kcx, kcy, kcz, -phi);
    g_amp[i] = A;
}

// ---------------- kernel 3: recip, 4 atoms/thread, single 6/SM wave ----------
// grid (N/1024, B, RNCH); kchunk = ceil(NK/RNCH) = 37; k-tile of 64.
#define RC_BLK 256
#define KTILE  64
__global__ void __launch_bounds__(RC_BLK, 6)
recip_kernel(const float* __restrict__ coords,
             const float* __restrict__ q,
             const float* __restrict__ volume,
             const float* __restrict__ bewald,
             float* __restrict__ out,
             int N, int NK, int kchunk, int BN) {
    __shared__ float4 st1[KTILE];
    __shared__ float  sam[KTILE];
    __shared__ int s_last;
    int b    = blockIdx.y;
    int base = blockIdx.x * (RC_BLK * 4);
    int k0 = blockIdx.z * kchunk;
    int k1 = min(k0 + kchunk, NK);

    float x0=0.f,y0=0.f,z0=0.f, x1=0.f,y1=0.f,z1=0.f;
    float x2=0.f,y2=0.f,z2=0.f, x3=0.f,y3=0.f,z3=0.f;
    {
        int n; const float* cp;
        n = base + 0*RC_BLK + threadIdx.x;
        if (n < N) { cp = coords + ((size_t)b*N + n)*3; x0=cp[0]; y0=cp[1]; z0=cp[2]; }
        n = base + 1*RC_BLK + threadIdx.x;
        if (n < N) { cp = coords + ((size_t)b*N + n)*3; x1=cp[0]; y1=cp[1]; z1=cp[2]; }
        n = base + 2*RC_BLK + threadIdx.x;
        if (n < N) { cp = coords + ((size_t)b*N + n)*3; x2=cp[0]; y2=cp[1]; z2=cp[2]; }
        n = base + 3*RC_BLK + threadIdx.x;
        if (n < N) { cp = coords + ((size_t)b*N + n)*3; x3=cp[0]; y3=cp[1]; z3=cp[2]; }
    }
    float acc0=0.f, acc1=0.f, acc2=0.f, acc3=0.f;

    for (int t = k0; t < k1; t += KTILE) {
        int nt = min(KTILE, k1 - t);
        if ((int)threadIdx.x < nt) {
            int k = t + threadIdx.x;
            st1[threadIdx.x] = g_t1[b * NK + k];
            sam[threadIdx.x] = g_amp[b * NK + k];
        }
        __syncthreads();
        #pragma unroll 2
        for (int j = 0; j < nt; j++) {
            float4 v = st1[j];            // kc.xyz, -phi
            float  A = sam[j];            // amplitude
            float th0 = fmaf(v.x, x0, fmaf(v.y, y0, fmaf(v.z, z0, v.w)));
            float th1 = fmaf(v.x, x1, fmaf(v.y, y1, fmaf(v.z, z1, v.w)));
            float th2 = fmaf(v.x, x2, fmaf(v.y, y2, fmaf(v.z, z2, v.w)));
            float th3 = fmaf(v.x, x3, fmaf(v.y, y3, fmaf(v.z, z3, v.w)));
            acc0 = fmaf(A, __cosf(th0), acc0);
            acc1 = fmaf(A, __cosf(th1), acc1);
            acc2 = fmaf(A, __cosf(th2), acc2);
            acc3 = fmaf(A, __cosf(th3), acc3);
        }
        __syncthreads();
    }
    {
        int n;
        n = base + 0*RC_BLK + threadIdx.x; if (n < N) atomicAdd(&g_recip[b*N + n], acc0);
        n = base + 1*RC_BLK + threadIdx.x; if (n < N) atomicAdd(&g_recip[b*N + n], acc1);
        n = base + 2*RC_BLK + threadIdx.x; if (n < N) atomicAdd(&g_recip[b*N + n], acc2);
        n = base + 3*RC_BLK + threadIdx.x; if (n < N) atomicAdd(&g_recip[b*N + n], acc3);
    }

    // ---- last z-block of this atom-slice finalizes & resets ----------------
    __threadfence();
    int slice = b * gridDim.x + blockIdx.x;
    if (threadIdx.x == 0) {
        int c = atomicAdd(&g_cnt_rc[slice], 1);
        s_last = (c == (int)gridDim.z - 1) ? 1 : 0;
    }
    __syncthreads();
    if (s_last) {
        const float BOHR = 1.8897261258369282f;
        const float INV_SQRT_PI = 0.5641895835477563f;
        float scale = BOHR / (CUDART_PI_F * volume[0]);
        float selfc = 2.0f * bewald[0] * BOHR * INV_SQRT_PI;
        #pragma unroll
        for (int a = 0; a < 4; a++) {
            int n = base + a * RC_BLK + threadIdx.x;
            if (n < N) {
                int i = b * N + n;
                float r = g_recip[i];
                g_recip[i] = 0.0f;                 // reset for next replay
                float qi = q[i];
                float phi = r * scale - qi * selfc;
                out[i] = 0.5f * qi * phi;
                out[BN + i] = phi;
            }
        }
        if (threadIdx.x == 0) g_cnt_rc[slice] = 0;
    }
}

// ---------------------------------------------------------------------------
extern "C" void kernel_launch(void* const* d_in, const int* in_sizes, int n_in,
                              void* d_out, int out_size) {
    const float* coords   = (const float*)d_in[0];
    const float* q        = (const float*)d_in[1];
    const float* cell_inv = (const float*)d_in[2];
    const float* kvec     = (const float*)d_in[3];
    const float* expfac   = (const float*)d_in[4];
    const float* volume   = (const float*)d_in[5];
    const float* bewald   = (const float*)d_in[6];
    float* out = (float*)d_out;

    int BN = in_sizes[1];       // B*N
    int NK = in_sizes[4];
    int B  = 2;                 // fixed shape for this problem
    int N  = BN / B;
    int BK = B * NK;

    // sf: 512 k / block, 74 atom-chunks -> 8*2*74 = 1184 blocks (R10)
    {
        int nchunk = (N + NCH - 1) / NCH;           // 56
        dim3 grid((NK + SF_BLK * 2 - 1) / (SF_BLK * 2), B, NCH);
        sf_kernel<<<grid, SF_BLK>>>(coords, q, kvec, cell_inv, N, NK, nchunk);
    }

    // reduce: fold partials + expfac -> (kc, -phi), A (R10)
    reduce_kernel<<<(BK + 255) / 256, 256>>>(kvec, cell_inv, expfac, NK, BK);

    // recip: 1024 atoms / block, 111 k-chunks -> 4*2*111 = 888 blocks = 6/SM
    {
        int kchunk = (NK + RNCH - 1) / RNCH;        // 37
        dim3 grid((N + RC_BLK * 4 - 1) / (RC_BLK * 4), B, RNCH);
        recip_kernel<<<grid, RC_BLK>>>(coords, q, volume, bewald, out,
                                       N, NK, kchunk, BN);
    }
}

// round 14
// speedup vs baseline: 1.0584x; 1.0584x over previous
#include <cuda_runtime.h>
#include <math_constants.h>

// ---------------------------------------------------------------------------
// EwaldReciprocal: B=2, N=4096, NK=4096 — 3 launches. R10 structure, with
// recip blocks doubled in work (kchunk 111, grid 592 = 4/SM) to amortize
// block prologue/epilogue over a longer main loop.
//   sf:     2 k/thread, unconditional partials (MUFU floor, ~19.8us).
//   reduce: partials + expfac -> amplitude-phase: A*cos(th - phi).
//   recip:  2 atoms/thread, 1 MUFU/theta; fused finalize + state reset.
// ---------------------------------------------------------------------------

#define NCH    74                  // sf z-chunks
#define RNCH   37                  // recip z-chunks: 8*2*37 = 592 = 4/SM wave
#define MAXK   4096
#define MAXBN  32768

__device__ float2 g_Spart[NCH * 2 * MAXK];     // [z][b][k]
__device__ float4 g_t1[2 * MAXK];              // (kc.x, kc.y, kc.z, -phi) [b][k]
__device__ float  g_amp[2 * MAXK];             // A [b][k]
__device__ float  g_recip[MAXBN];              // zero at entry; re-zeroed at end
__device__ int    g_cnt_rc[64];

// ---------------- kernel 1: structure factor partials (R10 exact) -----------
#define SF_BLK 256
__global__ void __launch_bounds__(SF_BLK, 8)
sf_kernel(const float* __restrict__ coords,
          const float* __restrict__ q,
          const float* __restrict__ kvec,
          const float* __restrict__ cell_inv,
          int N, int NK, int nchunk) {
    __shared__ float4 sh[SF_BLK];
    int b  = blockIdx.y;
    int z  = blockIdx.z;
    int kA = blockIdx.x * (SF_BLK * 2) + threadIdx.x;
    int kB = kA + SF_BLK;
    int n0 = z * nchunk;
    int n1 = min(n0 + nchunk, N);

    const float twopi = 6.283185307179586f;
    float ci[9];
    #pragma unroll
    for (int i = 0; i < 9; i++) ci[i] = __ldg(&cell_inv[i]);

    float4 kcA = make_float4(0.f, 0.f, 0.f, 0.f);
    float4 kcB = make_float4(0.f, 0.f, 0.f, 0.f);
    if (kA < NK) {
        float kx = kvec[kA * 3 + 0], ky = kvec[kA * 3 + 1], kz = kvec[kA * 3 + 2];
        kcA.x = twopi * (kx * ci[0] + ky * ci[3] + kz * ci[6]);
        kcA.y = twopi * (kx * ci[1] + ky * ci[4] + kz * ci[7]);
        kcA.z = twopi * (kx * ci[2] + ky * ci[5] + kz * ci[8]);
    }
    if (kB < NK) {
        float kx = kvec[kB * 3 + 0], ky = kvec[kB * 3 + 1], kz = kvec[kB * 3 + 2];
        kcB.x = twopi * (kx * ci[0] + ky * ci[3] + kz * ci[6]);
        kcB.y = twopi * (kx * ci[1] + ky * ci[4] + kz * ci[7]);
        kcB.z = twopi * (kx * ci[2] + ky * ci[5] + kz * ci[8]);
    }

    float sreA = 0.f, simA = 0.f, sreB = 0.f, simB = 0.f;

    for (int t = n0; t < n1; t += SF_BLK) {
        int nt = min(SF_BLK, n1 - t);
        if ((int)threadIdx.x < nt) {
            int n = t + threadIdx.x;
            const float* cp = coords + ((size_t)b * N + n) * 3;
            sh[threadIdx.x] = make_float4(cp[0], cp[1], cp[2], q[(size_t)b * N + n]);
        }
        __syncthreads();
        #pragma unroll 4
        for (int j = 0; j < nt; j++) {
            float4 a = sh[j];
            float thA = fmaf(kcA.x, a.x, fmaf(kcA.y, a.y, kcA.z * a.z));
            float thB = fmaf(kcB.x, a.x, fmaf(kcB.y, a.y, kcB.z * a.z));
            float sA, cA, sB, cB;
            __sincosf(thA, &sA, &cA);
            __sincosf(thB, &sB, &cB);
            sreA = fmaf(a.w, cA, sreA);
            simA = fmaf(a.w, sA, simA);
            sreB = fmaf(a.w, cB, sreB);
            simB = fmaf(a.w, sB, simB);
        }
        __syncthreads();
    }
    if (kA < NK) g_Spart[(z * 2 + b) * NK + kA] = make_float2(sreA, simA);
    if (kB < NK) g_Spart[(z * 2 + b) * NK + kB] = make_float2(sreB, simB);
}

// ---------------- kernel 2: reduce partials -> amplitude-phase (R10 exact) ---
__global__ void reduce_kernel(const float* __restrict__ kvec,
                              const float* __restrict__ cell_inv,
                              const float* __restrict__ expfac,
                              int NK, int BK) {
    int i = blockIdx.x * blockDim.x + threadIdx.x;
    if (i >= BK) return;
    int b = i / NK;
    int k = i - b * NK;

    float sre = 0.f, sim = 0.f;
    #pragma unroll 8
    for (int zz = 0; zz < NCH; zz++) {
        float2 p = g_Spart[(zz * 2 + b) * NK + k];
        sre += p.x; sim += p.y;
    }
    const float twopi = 6.283185307179586f;
    float ci[9];
    #pragma unroll
    for (int j = 0; j < 9; j++) ci[j] = __ldg(&cell_inv[j]);
    float kx = kvec[k * 3 + 0], ky = kvec[k * 3 + 1], kz = kvec[k * 3 + 2];
    float kcx = twopi * (kx * ci[0] + ky * ci[3] + kz * ci[6]);
    float kcy = twopi * (kx * ci[1] + ky * ci[4] + kz * ci[7]);
    float kcz = twopi * (kx * ci[2] + ky * ci[5] + kz * ci[8]);
    float e = expfac[k];
    float er = e * sre;
    float ei = e * sim;
    // er*cos(th) + ei*sin(th) = A*cos(th - phi)
    float A   = sqrtf(er * er + ei * ei);
    float phi = atan2f(ei, er);
    g_t1[i]  = make_float4(kcx, kcy, kcz, -phi);
    g_amp[i] = A;
}

// ---------------- kernel 3: recip (R10 loop, doubled kchunk) -----------------
// 2 atoms per thread; grid (N/512, B, RNCH); kchunk = 111.
#define RC_BLK 256
__global__ void __launch_bounds__(RC_BLK, 8)
recip_kernel(const float* __restrict__ coords,
             const float* __restrict__ q,
             const float* __restrict__ volume,
             const float* __restrict__ bewald,
             float* __restrict__ out,
             int N, int NK, int kchunk, int BN) {
    __shared__ float4 st1[RC_BLK];
    __shared__ float  sam[RC_BLK];
    __shared__ int s_last;
    int b  = blockIdx.y;
    int nA = blockIdx.x * (RC_BLK * 2) + threadIdx.x;
    int nB = nA + RC_BLK;
    int k0 = blockIdx.z * kchunk;
    int k1 = min(k0 + kchunk, NK);

    float xA = 0.f, yA = 0.f, zA = 0.f, xB = 0.f, yB = 0.f, zB = 0.f;
    if (nA < N) {
        const float* cp = coords + ((size_t)b * N + nA) * 3;
        xA = cp[0]; yA = cp[1]; zA = cp[2];
    }
    if (nB < N) {
        const float* cp = coords + ((size_t)b * N + nB) * 3;
        xB = cp[0]; yB = cp[1]; zB = cp[2];
    }
    float accA = 0.f, accB = 0.f;

    for (int t = k0; t < k1; t += RC_BLK) {
        int nt = min(RC_BLK, k1 - t);
        if ((int)threadIdx.x < nt) {
            int k = t + threadIdx.x;
            st1[threadIdx.x] = g_t1[b * NK + k];
            sam[threadIdx.x] = g_amp[b * NK + k];
        }
        __syncthreads();
        #pragma unroll 4
        for (int j = 0; j < nt; j++) {
            float4 v = st1[j];            // kc.xyz, -phi
            float  A = sam[j];            // amplitude
            float thA = fmaf(v.x, xA, fmaf(v.y, yA, fmaf(v.z, zA, v.w)));
            float thB = fmaf(v.x, xB, fmaf(v.y, yB, fmaf(v.z, zB, v.w)));
            accA = fmaf(A, __cosf(thA), accA);
            accB = fmaf(A, __cosf(thB), accB);
        }
        __syncthreads();
    }
    if (nA < N) atomicAdd(&g_recip[b * N + nA], accA);
    if (nB < N) atomicAdd(&g_recip[b * N + nB], accB);

    // ---- last z-block of this atom-slice finalizes & resets ----------------
    __threadfence();
    int slice = b * gridDim.x + blockIdx.x;
    if (threadIdx.x == 0) {
        int c = atomicAdd(&g_cnt_rc[slice], 1);
        s_last = (c == (int)gridDim.z - 1) ? 1 : 0;
    }
    __syncthreads();
    if (s_last) {
        const float BOHR = 1.8897261258369282f;
        const float INV_SQRT_PI = 0.5641895835477563f;
        float scale = BOHR / (CUDART_PI_F * volume[0]);
        float selfc = 2.0f * bewald[0] * BOHR * INV_SQRT_PI;
        int base = blockIdx.x * (RC_BLK * 2);
        #pragma unroll
        for (int a = 0; a < 2; a++) {
            int n = base + a * RC_BLK + threadIdx.x;
            if (n < N) {
                int i = b * N + n;
                float r = g_recip[i];
                g_recip[i] = 0.0f;                 // reset for next replay
                float qi = q[i];
                float phi = r * scale - qi * selfc;
                out[i] = 0.5f * qi * phi;
                out[BN + i] = phi;
            }
        }
        if (threadIdx.x == 0) g_cnt_rc[slice] = 0;
    }
}

// ---------------------------------------------------------------------------
extern "C" void kernel_launch(void* const* d_in, const int* in_sizes, int n_in,
                              void* d_out, int out_size) {
    const float* coords   = (const float*)d_in[0];
    const float* q        = (const float*)d_in[1];
    const float* cell_inv = (const float*)d_in[2];
    const float* kvec     = (const float*)d_in[3];
    const float* expfac   = (const float*)d_in[4];
    const float* volume   = (const float*)d_in[5];
    const float* bewald   = (const float*)d_in[6];
    float* out = (float*)d_out;

    int BN = in_sizes[1];       // B*N
    int NK = in_sizes[4];
    int B  = 2;                 // fixed shape for this problem
    int N  = BN / B;
    int BK = B * NK;

    // sf: 512 k / block, 74 atom-chunks -> 8*2*74 = 1184 blocks
    {
        int nchunk = (N + NCH - 1) / NCH;           // 56
        dim3 grid((NK + SF_BLK * 2 - 1) / (SF_BLK * 2), B, NCH);
        sf_kernel<<<grid, SF_BLK>>>(coords, q, kvec, cell_inv, N, NK, nchunk);
    }

    // reduce: fold partials + expfac -> (kc, -phi), A
    reduce_kernel<<<(BK + 255) / 256, 256>>>(kvec, cell_inv, expfac, NK, BK);

    // recip: 512 atoms / block, 37 k-chunks -> 8*2*37 = 592 blocks = 4/SM
    {
        int kchunk = (NK + RNCH - 1) / RNCH;        // 111
        dim3 grid((N + RC_BLK * 2 - 1) / (RC_BLK * 2), B, RNCH);
        recip_kernel<<<grid, RC_BLK>>>(coords, q, volume, bewald, out,
                                       N, NK, kchunk, BN);
    }
}